// round 16
// baseline (speedup 1.0000x reference)
#include <cuda_runtime.h>
#include <cuda_bf16.h>
#include <math.h>
#include <cstdint>

// Problem constants: B=2, S=2048, D=1024, H=16, HD=64
#define B_  2
#define S_  2048
#define D_  1024
#define H_  16
#define HD_ 64
#define SC2_   0.045084220f       // D^-0.5 * log2(e)
#define KTOT 1024

// ---------------------------------------------------------------------------
// Scratch (device globals)
// ---------------------------------------------------------------------------
__device__ __nv_bfloat16 g_qh[(size_t)B_*H_*S_*HD_];
__device__ __nv_bfloat16 g_kh[(size_t)B_*H_*S_*HD_];
__device__ __nv_bfloat16 g_vh[(size_t)B_*H_*S_*HD_], g_vl[(size_t)B_*H_*S_*HD_];
__device__ __nv_bfloat16 g_atth[(size_t)B_*S_*D_], g_attl[(size_t)B_*S_*D_];
__device__ __nv_bfloat16 g_xh[(size_t)B_*S_*D_],  g_xl[(size_t)B_*S_*D_];
__device__ __nv_bfloat16 g_wbh[(size_t)3*H_*HD_*D_], g_wbl[(size_t)3*H_*HD_*D_];
__device__ __nv_bfloat16 g_wph[(size_t)D_*D_],    g_wpl[(size_t)D_*D_];

// ---------------------------------------------------------------------------
// PTX helpers (sm_80+ only; compile clean under compute_103)
// ---------------------------------------------------------------------------
__device__ __forceinline__ uint32_t smem_to_u32(const void* p) {
    uint32_t a;
    asm("{ .reg .u64 t; cvta.to.shared.u64 t, %1; cvt.u32.u64 %0, t; }" : "=r"(a) : "l"(p));
    return a;
}
#define LDSM4(r, addr) \
    asm volatile("ldmatrix.sync.aligned.m8n8.x4.shared.b16 {%0,%1,%2,%3}, [%4];" \
        : "=r"((r)[0]), "=r"((r)[1]), "=r"((r)[2]), "=r"((r)[3]) : "r"(addr))
#define LDSM4T(r, addr) \
    asm volatile("ldmatrix.sync.aligned.m8n8.x4.trans.shared.b16 {%0,%1,%2,%3}, [%4];" \
        : "=r"((r)[0]), "=r"((r)[1]), "=r"((r)[2]), "=r"((r)[3]) : "r"(addr))
#define MMA_BF16(c, a, b0, b1) \
    asm volatile("mma.sync.aligned.m16n8k16.row.col.f32.bf16.bf16.f32 " \
        "{%0,%1,%2,%3}, {%4,%5,%6,%7}, {%8,%9}, {%0,%1,%2,%3};" \
        : "+f"((c)[0]), "+f"((c)[1]), "+f"((c)[2]), "+f"((c)[3]) \
        : "r"((a)[0]), "r"((a)[1]), "r"((a)[2]), "r"((a)[3]), "r"(b0), "r"(b1))
#define CP16(saddr, gptr) \
    asm volatile("cp.async.cg.shared.global [%0], [%1], 16;" \
        :: "r"((uint32_t)(saddr)), "l"(gptr))
#define CP_COMMIT() asm volatile("cp.async.commit_group;" ::: "memory")
#define CP_WAIT(n)  asm volatile("cp.async.wait_group %0;" :: "n"(n) : "memory")

__device__ __forceinline__ uint32_t pack_bf16(float lo, float hi) {
    __nv_bfloat162 t = __floats2bfloat162_rn(lo, hi);
    return *(uint32_t*)&t;
}
// fast exp2: rint split + deg-5 poly; input always <= 0.
__device__ __forceinline__ float exp2f_fast(float t) {
    t = fmaxf(t, -120.f);
    int ni = __float2int_rn(t);
    float f = t - (float)ni;
    float r = 1.f + f * (0.69314718f + f * (0.24022651f + f * (0.05550411f
               + f * (0.00961812f + f * 0.00133336f))));
    return r * __int_as_float((ni + 127) << 23);
}

// ---------------------------------------------------------------------------
// Split kernel: fp32 -> bf16 hi + bf16 residual (x and Wp)
// ---------------------------------------------------------------------------
__global__ __launch_bounds__(256) void split_kernel(const float* __restrict__ src,
                                                    int mode, int n4)
{
    int i = blockIdx.x * 256 + threadIdx.x;
    if (i >= n4) return;
    __nv_bfloat16* dh = (mode == 0) ? g_xh : g_wph;
    __nv_bfloat16* dl = (mode == 0) ? g_xl : g_wpl;

    float4 v = ((const float4*)src)[i];
    __nv_bfloat16 h0 = __float2bfloat16(v.x);
    __nv_bfloat16 h1 = __float2bfloat16(v.y);
    __nv_bfloat16 h2 = __float2bfloat16(v.z);
    __nv_bfloat16 h3 = __float2bfloat16(v.w);
    __nv_bfloat16 l0 = __float2bfloat16(v.x - __bfloat162float(h0));
    __nv_bfloat16 l1 = __float2bfloat16(v.y - __bfloat162float(h1));
    __nv_bfloat16 l2 = __float2bfloat16(v.z - __bfloat162float(h2));
    __nv_bfloat16 l3 = __float2bfloat16(v.w - __bfloat162float(h3));
    __nv_bfloat16 hs[4] = {h0, h1, h2, h3};
    __nv_bfloat16 ls[4] = {l0, l1, l2, l3};
    ((uint2*)dh)[i] = *(uint2*)hs;
    ((uint2*)dl)[i] = *(uint2*)ls;
}

// ---------------------------------------------------------------------------
// convw: W[h][k][e] -> Wbig^T[n][k] (n = which*1024 + h*64 + e), hi/lo split.
// Tiled smem transpose: coalesced 256B row reads, conflict-free column reads
// ([32][65] fp32: bank = (k*65+e)%32 = (k+e)%32, distinct across the warp).
// ---------------------------------------------------------------------------
__global__ __launch_bounds__(256) void convw_kernel(const float* __restrict__ Wq,
                                                    const float* __restrict__ Wk,
                                                    const float* __restrict__ Wv)
{
    __shared__ float tile[32][65];
    const int bid   = blockIdx.x;       // 0..1535
    const int h3    = bid >> 5;         // 0..47
    const int ktile = bid & 31;
    const int which = h3 >> 4;
    const int h     = h3 & 15;
    const int k0    = ktile * 32;
    const float* W = (which == 0 ? Wq : which == 1 ? Wk : Wv) + (size_t)h * D_ * HD_;
    const int t = threadIdx.x;

    {   // load 32 k-rows x 64 e (coalesced 32B per thread)
        const int kr = t >> 3;
        const int e0 = (t & 7) * 8;
        const float* src = W + (size_t)(k0 + kr) * HD_ + e0;
        #pragma unroll
        for (int i = 0; i < 8; i++) tile[kr][e0 + i] = src[i];
    }
    __syncthreads();
    {   // write transposed, hi/lo split, 16B chunks
        const int e  = t >> 2;
        const int ks = (t & 3) * 8;
        const int n  = which * 1024 + h * 64 + e;
        __nv_bfloat16 hb[8], lb[8];
        #pragma unroll
        for (int i = 0; i < 8; i++) {
            float v = tile[ks + i][e];
            __nv_bfloat16 hi = __float2bfloat16(v);
            hb[i] = hi;
            lb[i] = __float2bfloat16(v - __bfloat162float(hi));
        }
        *(uint4*)&g_wbh[(size_t)n * D_ + k0 + ks] = *(uint4*)hb;
        *(uint4*)&g_wbl[(size_t)n * D_ + k0 + ks] = *(uint4*)lb;
    }
}

// ---------------------------------------------------------------------------
// Warp-MMA GEMM, bf16x3 split (ALL blocks — q/k accuracy is load-bearing for
// the score path; see round-14 post-mortem), cp.async 3-stage pipeline.
// mode 0: QKV (emit q/k hi only, v hi/lo)   mode 1: out-proj (+bias, fp32)
// ---------------------------------------------------------------------------
#define NST 3
#define TB_AH 0
#define TB_AL 8192
#define TB_BH 16384
#define TB_BL 24576
#define STG_B 32768
#define GEMM_SMEM (NST * STG_B)   // 98304

__device__ __forceinline__ uint32_t swz(int row, int chunk) {
    int sw = chunk ^ ((row >> 1) & 3) ^ ((row >> 3) & 1);
    return (uint32_t)((row << 6) + (sw << 4));
}

__global__ __launch_bounds__(256, 2) void gemm_mma(int mode,
                                                   const float* __restrict__ bias,
                                                   float* __restrict__ Cout)
{
    extern __shared__ __nv_bfloat16 dsm[];
    const uint32_t ub = smem_to_u32(dsm);

    const int tid  = threadIdx.x;
    const int lane = tid & 31;
    const int wid  = tid >> 5;
    const int warp_m = wid >> 2;
    const int warp_n = wid & 3;
    const int n0 = blockIdx.x * 128;
    const int m0 = blockIdx.y * 128;

    const __nv_bfloat16* Ah = mode ? g_atth : g_xh;
    const __nv_bfloat16* Al = mode ? g_attl : g_xl;
    const __nv_bfloat16* Bh = mode ? g_wph  : g_wbh;
    const __nv_bfloat16* Bl = mode ? g_wpl  : g_wbl;

    const int lrow = tid >> 1;
    const int lseg = tid & 1;
    const __nv_bfloat16* ga_h = Ah + (size_t)(m0 + lrow) * KTOT;
    const __nv_bfloat16* ga_l = Al + (size_t)(m0 + lrow) * KTOT;
    const __nv_bfloat16* gb_h = Bh + (size_t)(n0 + lrow) * KTOT;
    const __nv_bfloat16* gb_l = Bl + (size_t)(n0 + lrow) * KTOT;
    const uint32_t s0 = swz(lrow, 2 * lseg);
    const uint32_t s1 = swz(lrow, 2 * lseg + 1);
    const int gofs = lseg * 16;

    const int lrm = lane & 15;
    const int lck = (lane >> 4);

    float acc[4][4][4];
    #pragma unroll
    for (int i = 0; i < 4; i++)
        #pragma unroll
        for (int j = 0; j < 4; j++)
            #pragma unroll
            for (int r = 0; r < 4; r++) acc[i][j][r] = 0.f;

    #pragma unroll
    for (int ps = 0; ps < 2; ps++) {
        const uint32_t sb = ub + ps * STG_B;
        const int k0 = ps * 32 + gofs;
        CP16(sb + TB_AH + s0, ga_h + k0);      CP16(sb + TB_AH + s1, ga_h + k0 + 8);
        CP16(sb + TB_AL + s0, ga_l + k0);      CP16(sb + TB_AL + s1, ga_l + k0 + 8);
        CP16(sb + TB_BH + s0, gb_h + k0);      CP16(sb + TB_BH + s1, gb_h + k0 + 8);
        CP16(sb + TB_BL + s0, gb_l + k0);      CP16(sb + TB_BL + s1, gb_l + k0 + 8);
        CP_COMMIT();
    }

    const int NKC = KTOT / 32;
    int slot = 0, wslot = 2;
    for (int kc = 0; kc < NKC; kc++) {
        CP_WAIT(1);
        __syncthreads();

        if (kc + 2 < NKC) {
            const uint32_t sb = ub + wslot * STG_B;
            const int k0 = (kc + 2) * 32 + gofs;
            CP16(sb + TB_AH + s0, ga_h + k0);      CP16(sb + TB_AH + s1, ga_h + k0 + 8);
            CP16(sb + TB_AL + s0, ga_l + k0);      CP16(sb + TB_AL + s1, ga_l + k0 + 8);
            CP16(sb + TB_BH + s0, gb_h + k0);      CP16(sb + TB_BH + s1, gb_h + k0 + 8);
            CP16(sb + TB_BL + s0, gb_l + k0);      CP16(sb + TB_BL + s1, gb_l + k0 + 8);
        }
        CP_COMMIT();

        const uint32_t us = ub + slot * STG_B;
        #pragma unroll
        for (int ks = 0; ks < 2; ks++) {
            const int chunk = ks * 2 + lck;
            uint32_t afh[4][4], afl[4][4];
            uint32_t bfh[2][4], bfl[2][4];
            #pragma unroll
            for (int mt = 0; mt < 4; mt++) {
                const uint32_t off = swz(warp_m * 64 + mt * 16 + lrm, chunk);
                LDSM4(afh[mt], us + TB_AH + off);
                LDSM4(afl[mt], us + TB_AL + off);
            }
            #pragma unroll
            for (int np = 0; np < 2; np++) {
                const uint32_t off = swz(warp_n * 32 + np * 16 + lrm, chunk);
                LDSM4(bfh[np], us + TB_BH + off);
                LDSM4(bfl[np], us + TB_BL + off);
            }
            #pragma unroll
            for (int mt = 0; mt < 4; mt++) {
                #pragma unroll
                for (int nt = 0; nt < 4; nt++) {
                    const int np = nt >> 1, sel = nt & 1;
                    MMA_BF16(acc[mt][nt], afh[mt], bfh[np][sel], bfh[np][sel + 2]);
                    MMA_BF16(acc[mt][nt], afh[mt], bfl[np][sel], bfl[np][sel + 2]);
                    MMA_BF16(acc[mt][nt], afl[mt], bfh[np][sel], bfh[np][sel + 2]);
                }
            }
        }
        slot = (slot == 2) ? 0 : slot + 1;
        wslot = (wslot == 2) ? 0 : wslot + 1;
    }

    // ------------------------------ epilogue ------------------------------
    #pragma unroll
    for (int mt = 0; mt < 4; mt++) {
        #pragma unroll
        for (int nt = 0; nt < 4; nt++) {
            const int mrow = m0 + warp_m * 64 + mt * 16 + (lane >> 2);
            const int ncol = n0 + warp_n * 32 + nt * 8 + (lane & 3) * 2;
            if (mode == 1) {
                const float b0 = bias[ncol], b1 = bias[ncol + 1];
                float2 v0 = make_float2(acc[mt][nt][0] + b0, acc[mt][nt][1] + b1);
                float2 v1 = make_float2(acc[mt][nt][2] + b0, acc[mt][nt][3] + b1);
                *(float2*)(Cout + (size_t)mrow * D_ + ncol)       = v0;
                *(float2*)(Cout + (size_t)(mrow + 8) * D_ + ncol) = v1;
            } else {
                const int which = ncol >> 10;
                const int h = (ncol >> 6) & 15;
                const int e = ncol & 63;
                __nv_bfloat16* bhp = (which == 0 ? g_qh : which == 1 ? g_kh : g_vh);
                #pragma unroll
                for (int half = 0; half < 2; half++) {
                    const int mr = mrow + half * 8;
                    const float a0 = acc[mt][nt][half * 2 + 0];
                    const float a1 = acc[mt][nt][half * 2 + 1];
                    const int b = mr >> 11, s = mr & 2047;
                    const size_t base = (((size_t)(b * H_ + h) * S_) + s) * HD_ + e;
                    *(uint32_t*)&bhp[base] = pack_bf16(a0, a1);
                    if (which == 2) {   // v needs the residual too
                        const float h0f = __bfloat162float(__float2bfloat16(a0));
                        const float h1f = __bfloat162float(__float2bfloat16(a1));
                        *(uint32_t*)&g_vl[base] = pack_bf16(a0 - h0f, a1 - h1f);
                    }
                }
            }
        }
    }
}

// ---------------------------------------------------------------------------
// MMA flash attention, KV tile = 64. Q/K plain bf16 (1-pass QK), V + P bf16x3.
// BOTH K and V double-buffered -> single cp.async group per tile, ONE
// wait+sync per tile; group(kt+1) issued at top of tile kt.
// Block = 128 q rows of one (b,h); 256 thr / 8 warps; 2 CTAs/SM (55.3KB smem).
// ---------------------------------------------------------------------------
#define ATPAD 72
#define AKB(kb)  ((kb) * 64 * ATPAD)              // K hi buf (Q staging spans both)
#define AVHB(kb) ((2 + 2*(kb)) * 64 * ATPAD)
#define AVLB(kb) ((3 + 2*(kb)) * 64 * ATPAD)
#define ATT_SMEM (6 * 64 * ATPAD * 2)             // 55296 bytes

__global__ __launch_bounds__(256, 2) void attn_mma_kernel()
{
    extern __shared__ __nv_bfloat16 sm[];
    const uint32_t uS = smem_to_u32(sm);
    const int qt  = (int)gridDim.x - 1 - (int)blockIdx.x;   // heavy blocks first
    const int bh  = blockIdx.y;
    const int tid = threadIdx.x;
    const int lane = tid & 31;
    const int wid  = tid >> 5;
    const int m0g = qt * 128;

    const __nv_bfloat16* Qh = g_qh + (size_t)bh * S_ * HD_;
    const __nv_bfloat16* Kh = g_kh + (size_t)bh * S_ * HD_;
    const __nv_bfloat16* Vh = g_vh + (size_t)bh * S_ * HD_;
    const __nv_bfloat16* Vl = g_vl + (size_t)bh * S_ * HD_;

    const int lrm  = lane & 15;
    const int lck  = (lane >> 4) * 8;

    // KV loader indices: 256 threads cover 64 rows x 4 chunk-pairs
    const int krow = tid >> 2;          // 0..63
    const int kseg = tid & 3;
    const uint32_t kvo = 2u * (krow * ATPAD + kseg * 16);

    // ---- stage Q (128 rows) across both K bufs, build Q fragments ----
    {
        const int row = tid >> 1, half = tid & 1;
        const __nv_bfloat16* q_h = Qh + (size_t)(m0g + row) * HD_ + half * 32;
        const uint32_t d = 2u * (row * ATPAD + half * 32);
        #pragma unroll
        for (int c = 0; c < 4; c++)
            CP16(uS + d + c * 16, q_h + c * 8);
        CP_COMMIT();
        CP_WAIT(0);
        __syncthreads();
    }
    uint32_t aQh[4][4];
    #pragma unroll
    for (int dk = 0; dk < 4; dk++) {
        const uint32_t off = 2u * ((wid * 16 + lrm) * ATPAD + dk * 16 + lck);
        LDSM4(aQh[dk], uS + off);
    }
    __syncthreads();    // Q frag reads done before K(0) overwrites buf0

    // ---- prologue: issue {K,V}(0) into buffers 0 as one group ----
    {
        const __nv_bfloat16* k_h = Kh + (size_t)krow * HD_ + kseg * 16;
        const __nv_bfloat16* v_h = Vh + (size_t)krow * HD_ + kseg * 16;
        const __nv_bfloat16* v_l = Vl + (size_t)krow * HD_ + kseg * 16;
        CP16(uS + 2*AKB(0)  + kvo,      k_h);
        CP16(uS + 2*AKB(0)  + kvo + 16, k_h + 8);
        CP16(uS + 2*AVHB(0) + kvo,      v_h);
        CP16(uS + 2*AVHB(0) + kvo + 16, v_h + 8);
        CP16(uS + 2*AVLB(0) + kvo,      v_l);
        CP16(uS + 2*AVLB(0) + kvo + 16, v_l + 8);
        CP_COMMIT();
    }

    float accO[8][4];
    #pragma unroll
    for (int i = 0; i < 8; i++)
        #pragma unroll
        for (int r = 0; r < 4; r++) accO[i][r] = 0.f;
    float m0s = -1e30f, m1s = -1e30f, l0s = 0.f, l1s = 0.f;

    const int r0g = m0g + wid * 16 + (lane >> 2);
    const int r1g = r0g + 8;
    const int ntiles = 2 * (qt + 1);

    for (int kt = 0; kt < ntiles; kt++) {
        const int j0 = kt * 64;
        const int kb = kt & 1;
        const uint32_t ukh = uS + 2u * AKB(kb);
        const uint32_t uvh = uS + 2u * AVHB(kb);
        const uint32_t uvl = uS + 2u * AVLB(kb);

        CP_WAIT(0);        // {K,V}(kt) landed
        __syncthreads();   // visible to all warps; prev-tile reads complete

        // issue {K,V}(kt+1) into the other buffers (read last at kt-1 -> safe)
        if (kt + 1 < ntiles) {
            const int j1 = (kt + 1) * 64;
            const int nb = kb ^ 1;
            const __nv_bfloat16* k_h = Kh + (size_t)(j1 + krow) * HD_ + kseg * 16;
            const __nv_bfloat16* v_h = Vh + (size_t)(j1 + krow) * HD_ + kseg * 16;
            const __nv_bfloat16* v_l = Vl + (size_t)(j1 + krow) * HD_ + kseg * 16;
            CP16(uS + 2*AKB(nb)  + kvo,      k_h);
            CP16(uS + 2*AKB(nb)  + kvo + 16, k_h + 8);
            CP16(uS + 2*AVHB(nb) + kvo,      v_h);
            CP16(uS + 2*AVHB(nb) + kvo + 16, v_h + 8);
            CP16(uS + 2*AVLB(nb) + kvo,      v_l);
            CP16(uS + 2*AVLB(nb) + kvo + 16, v_l + 8);
        }
        CP_COMMIT();

        // ---- QK (1-pass bf16): S[16 x 64] per warp ----
        float accS[8][4];
        #pragma unroll
        for (int i = 0; i < 8; i++)
            #pragma unroll
            for (int r = 0; r < 4; r++) accS[i][r] = 0.f;

        #pragma unroll
        for (int dk = 0; dk < 4; dk++) {
            #pragma unroll
            for (int jc = 0; jc < 4; jc++) {
                uint32_t kh[4];
                const uint32_t off = 2u * ((jc * 16 + lrm) * ATPAD + dk * 16 + lck);
                LDSM4(kh, ukh + off);
                MMA_BF16(accS[2*jc],   aQh[dk], kh[0], kh[2]);
                MMA_BF16(accS[2*jc+1], aQh[dk], kh[1], kh[3]);
            }
        }

        // ---- softmax (base-2, no MUFU) ----
        const bool diag = (kt >= 2 * qt);
        float mx0 = -1e30f, mx1 = -1e30f;
        #pragma unroll
        for (int nt = 0; nt < 8; nt++) {
            const int jb = j0 + nt * 8 + (lane & 3) * 2;
            float c0 = accS[nt][0] * SC2_;
            float c1 = accS[nt][1] * SC2_;
            float c2 = accS[nt][2] * SC2_;
            float c3 = accS[nt][3] * SC2_;
            if (diag) {
                if (jb     > r0g) c0 = -1e30f;
                if (jb + 1 > r0g) c1 = -1e30f;
                if (jb     > r1g) c2 = -1e30f;
                if (jb + 1 > r1g) c3 = -1e30f;
            }
            accS[nt][0] = c0; accS[nt][1] = c1; accS[nt][2] = c2; accS[nt][3] = c3;
            mx0 = fmaxf(mx0, fmaxf(c0, c1));
            mx1 = fmaxf(mx1, fmaxf(c2, c3));
        }
        mx0 = fmaxf(mx0, __shfl_xor_sync(0xffffffffu, mx0, 1));
        mx0 = fmaxf(mx0, __shfl_xor_sync(0xffffffffu, mx0, 2));
        mx1 = fmaxf(mx1, __shfl_xor_sync(0xffffffffu, mx1, 1));
        mx1 = fmaxf(mx1, __shfl_xor_sync(0xffffffffu, mx1, 2));

        const float mn0 = fmaxf(m0s, mx0);
        const float mn1 = fmaxf(m1s, mx1);
        const float al0 = exp2f_fast(m0s - mn0);
        const float al1 = exp2f_fast(m1s - mn1);
        m0s = mn0; m1s = mn1;

        float ls0 = 0.f, ls1 = 0.f;
        #pragma unroll
        for (int nt = 0; nt < 8; nt++) {
            float p0 = exp2f_fast(accS[nt][0] - mn0);
            float p1 = exp2f_fast(accS[nt][1] - mn0);
            float p2 = exp2f_fast(accS[nt][2] - mn1);
            float p3v = exp2f_fast(accS[nt][3] - mn1);
            accS[nt][0] = p0; accS[nt][1] = p1; accS[nt][2] = p2; accS[nt][3] = p3v;
            ls0 += p0 + p1;
            ls1 += p2 + p3v;
        }
        ls0 += __shfl_xor_sync(0xffffffffu, ls0, 1);
        ls0 += __shfl_xor_sync(0xffffffffu, ls0, 2);
        ls1 += __shfl_xor_sync(0xffffffffu, ls1, 1);
        ls1 += __shfl_xor_sync(0xffffffffu, ls1, 2);
        l0s = l0s * al0 + ls0;
        l1s = l1s * al1 + ls1;

        #pragma unroll
        for (int i = 0; i < 8; i++) {
            accO[i][0] *= al0; accO[i][1] *= al0;
            accO[i][2] *= al1; accO[i][3] *= al1;
        }

        // ---- PV (3-pass split): accO += P @ V ----
        #pragma unroll
        for (int kt2 = 0; kt2 < 4; kt2++) {
            uint32_t aPh[4], aPl[4];
            {
                const float p00 = accS[2*kt2][0],   p01 = accS[2*kt2][1];
                const float p02 = accS[2*kt2][2],   p03 = accS[2*kt2][3];
                const float p10 = accS[2*kt2+1][0], p11 = accS[2*kt2+1][1];
                const float p12 = accS[2*kt2+1][2], p13 = accS[2*kt2+1][3];
                aPh[0] = pack_bf16(p00, p01);
                aPh[1] = pack_bf16(p02, p03);
                aPh[2] = pack_bf16(p10, p11);
                aPh[3] = pack_bf16(p12, p13);
                aPl[0] = pack_bf16(p00 - __bfloat162float(__float2bfloat16(p00)),
                                   p01 - __bfloat162float(__float2bfloat16(p01)));
                aPl[1] = pack_bf16(p02 - __bfloat162float(__float2bfloat16(p02)),
                                   p03 - __bfloat162float(__float2bfloat16(p03)));
                aPl[2] = pack_bf16(p10 - __bfloat162float(__float2bfloat16(p10)),
                                   p11 - __bfloat162float(__float2bfloat16(p11)));
                aPl[3] = pack_bf16(p12 - __bfloat162float(__float2bfloat16(p12)),
                                   p13 - __bfloat162float(__float2bfloat16(p13)));
            }
            const uint32_t vbase = 2u * ((kt2 * 16 + lrm) * ATPAD + lck);
            #pragma unroll
            for (int g = 0; g < 4; g++) {
                uint32_t vh[4], vl[4];
                const uint32_t off = vbase + 2u * (g * 16);
                LDSM4T(vh, uvh + off);
                LDSM4T(vl, uvl + off);
                MMA_BF16(accO[2*g],   aPh, vh[0], vh[1]);
                MMA_BF16(accO[2*g+1], aPh, vh[2], vh[3]);
                MMA_BF16(accO[2*g],   aPh, vl[0], vl[1]);
                MMA_BF16(accO[2*g+1], aPh, vl[2], vl[3]);
                MMA_BF16(accO[2*g],   aPl, vh[0], vh[1]);
                MMA_BF16(accO[2*g+1], aPl, vh[2], vh[3]);
            }
        }
    }

    // ---- epilogue: normalize, split hi/lo, write concat layout ----
    const int b = bh >> 4;
    const int h = bh & 15;
    const float inv0 = 1.f / l0s;
    const float inv1 = 1.f / l1s;
    #pragma unroll
    for (int nt = 0; nt < 8; nt++) {
        const int e = nt * 8 + (lane & 3) * 2;
        #pragma unroll
        for (int half = 0; half < 2; half++) {
            const int s = (half == 0) ? r0g : r1g;
            const float sc = (half == 0) ? inv0 : inv1;
            const float a0 = accO[nt][half * 2 + 0] * sc;
            const float a1 = accO[nt][half * 2 + 1] * sc;
            const size_t base = ((size_t)b * S_ + s) * D_ + h * HD_ + e;
            const float h0f = __bfloat162float(__float2bfloat16(a0));
            const float h1f = __bfloat162float(__float2bfloat16(a1));
            *(uint32_t*)&g_atth[base] = pack_bf16(a0, a1);
            *(uint32_t*)&g_attl[base] = pack_bf16(a0 - h0f, a1 - h1f);
        }
    }
}

// ---------------------------------------------------------------------------
// Launch
// ---------------------------------------------------------------------------
extern "C" void kernel_launch(void* const* d_in, const int* in_sizes, int n_in,
                              void* d_out, int out_size)
{
    const float* x  = (const float*)d_in[0];
    const float* Wq = (const float*)d_in[1];
    const float* Wk = (const float*)d_in[2];
    const float* Wv = (const float*)d_in[3];
    const float* Wp = (const float*)d_in[4];
    const float* bp = (const float*)d_in[5];
    float* out = (float*)d_out;
    (void)in_sizes; (void)n_in; (void)out_size;

    cudaFuncSetAttribute(gemm_mma,
                         cudaFuncAttributeMaxDynamicSharedMemorySize, GEMM_SMEM);
    cudaFuncSetAttribute(attn_mma_kernel,
                         cudaFuncAttributeMaxDynamicSharedMemorySize, ATT_SMEM);

    const int x4 = (B_ * S_ * D_) / 4;
    split_kernel<<<(x4 + 255) / 256, 256>>>(x, 0, x4);
    convw_kernel<<<3 * H_ * (D_ / 32), 256>>>(Wq, Wk, Wv);
    const int w4 = (D_ * D_) / 4;
    split_kernel<<<(w4 + 255) / 256, 256>>>(Wp, 2, w4);

    // QKV: C[4096, 3072], 128x128 tiles -> bf16 q/k (hi), v (hi/lo)
    gemm_mma<<<dim3((3 * H_ * HD_) / 128, (B_ * S_) / 128), 256, GEMM_SMEM>>>(
        0, nullptr, nullptr);

    // MMA flash attention -> g_atth/g_attl
    attn_mma_kernel<<<dim3(S_ / 128, B_ * H_), 256, ATT_SMEM>>>();

    // out projection
    gemm_mma<<<dim3(D_ / 128, (B_ * S_) / 128), 256, GEMM_SMEM>>>(1, bp, out);
}